// round 6
// baseline (speedup 1.0000x reference)
#include <cuda_runtime.h>
#include <math.h>

#define EPSV 1e-6f
#define B_ 8
#define N_ 4096
#define P_ 16
#define H_ 128
#define NC_ 64                 // points per chunk
#define NCHUNKS_ (N_/NC_)      // 64
#define NCG_ 8                 // chunk groups (8 chunks each)
#define HIDDEN_ 128
#define RDIM_ 64
#define PH_ (P_*H_)            // 2048

// scratch
__device__ __align__(16) float g_part[B_ * NCHUNKS_ * 3 * PH_];     // 12.6 MB
__device__ float g_massp[B_ * NCHUNKS_ * P_];
// second-level partials: [row(128)][stat(3)][cg(8)*128 + h]
__device__ __align__(16) float g_part2[128 * 3 * NCG_ * H_];        // 1.5 MB

__device__ __forceinline__ float neg_inf() { return __int_as_float(0xff800000u); }

// ---------------------------------------------------------------------------
// Phase 1: per-(b, n-chunk) weighted sum / sumsq / masked-max partials
// ---------------------------------------------------------------------------
__global__ __launch_bounds__(128) void phase1_kernel(
    const float* __restrict__ pf, const float* __restrict__ am)
{
    const int c = blockIdx.x;      // chunk 0..63
    const int b = blockIdx.y;      // batch 0..7
    const int t = threadIdx.x;     // h lane 0..127

    __shared__ __align__(16) float a_sm[NC_][P_];
    __shared__ __align__(16) float q_sm[NC_][P_];   // bias: 0 if active, -inf if not

    {
        const float4* ap = (const float4*)(am + (size_t)(b * N_ + c * NC_) * P_);
        #pragma unroll
        for (int i = 0; i < 2; i++) {
            int idx = i * 128 + t;               // 256 float4 total
            float4 v = ap[idx];
            ((float4*)a_sm)[idx] = v;
            float4 qq;
            qq.x = (v.x <= EPSV) ? neg_inf() : 0.f;
            qq.y = (v.y <= EPSV) ? neg_inf() : 0.f;
            qq.z = (v.z <= EPSV) ? neg_inf() : 0.f;
            qq.w = (v.w <= EPSV) ? neg_inf() : 0.f;
            ((float4*)q_sm)[idx] = qq;
        }
    }
    __syncthreads();

    float s1[P_], s2[P_], mx[P_];
    #pragma unroll
    for (int p = 0; p < P_; p++) { s1[p] = 0.f; s2[p] = 0.f; mx[p] = neg_inf(); }

    const float* pfp = pf + (size_t)(b * N_ + c * NC_) * H_ + t;

    #pragma unroll 4
    for (int n = 0; n < NC_; n++) {
        float v  = pfp[n * H_];
        float vv = v * v;
        float4 a0 = *(const float4*)&a_sm[n][0];
        float4 a1 = *(const float4*)&a_sm[n][4];
        float4 a2 = *(const float4*)&a_sm[n][8];
        float4 a3 = *(const float4*)&a_sm[n][12];
        float4 q0 = *(const float4*)&q_sm[n][0];
        float4 q1 = *(const float4*)&q_sm[n][4];
        float4 q2 = *(const float4*)&q_sm[n][8];
        float4 q3 = *(const float4*)&q_sm[n][12];
#define CORE(idx, A, Q) { \
        s1[idx] = fmaf((A), v,  s1[idx]); \
        s2[idx] = fmaf((A), vv, s2[idx]); \
        mx[idx] = fmaxf(mx[idx], fmaf((A), v, (Q))); }
        CORE(0,  a0.x, q0.x) CORE(1,  a0.y, q0.y) CORE(2,  a0.z, q0.z) CORE(3,  a0.w, q0.w)
        CORE(4,  a1.x, q1.x) CORE(5,  a1.y, q1.y) CORE(6,  a1.z, q1.z) CORE(7,  a1.w, q1.w)
        CORE(8,  a2.x, q2.x) CORE(9,  a2.y, q2.y) CORE(10, a2.z, q2.z) CORE(11, a2.w, q2.w)
        CORE(12, a3.x, q3.x) CORE(13, a3.y, q3.y) CORE(14, a3.z, q3.z) CORE(15, a3.w, q3.w)
#undef CORE
    }

    float* base = g_part + (size_t)((b * NCHUNKS_ + c) * 3) * PH_ + t;
    #pragma unroll
    for (int p = 0; p < P_; p++) {
        base[0 * PH_ + p * H_] = s1[p];
        base[1 * PH_ + p * H_] = s2[p];
        base[2 * PH_ + p * H_] = mx[p];
    }

    if (t < P_) {
        float s = 0.f;
        #pragma unroll 8
        for (int n = 0; n < NC_; n++) s += a_sm[n][t];
        g_massp[(b * NCHUNKS_ + c) * P_ + t] = s;
    }
}

// ---------------------------------------------------------------------------
// Reduce: fold 64 chunks -> 8 chunk-groups with high grid parallelism.
// grid (8 cg, 128 rows), 128 threads (h). Streams g_part (12.6 MB) from DRAM.
// ---------------------------------------------------------------------------
__global__ __launch_bounds__(128) void reduce_kernel()
{
    const int cg  = blockIdx.x;        // 0..7
    const int row = blockIdx.y;        // 0..127
    const int b   = row >> 4;
    const int p   = row & 15;
    const int t   = threadIdx.x;       // h

    float s1 = 0.f, s2 = 0.f, mx = neg_inf();
    const float* base = g_part
        + (size_t)((b * NCHUNKS_ + cg * 8) * 3) * PH_ + p * H_ + t;
    #pragma unroll
    for (int cc = 0; cc < 8; cc++) {
        const float* bb = base + (size_t)cc * 3 * PH_;
        s1 += bb[0];
        s2 += bb[PH_];
        mx = fmaxf(mx, bb[2 * PH_]);
    }
    float* o = g_part2 + (size_t)row * (3 * NCG_ * H_) + cg * H_ + t;
    o[0]                = s1;
    o[NCG_ * H_]        = s2;
    o[2 * NCG_ * H_]    = mx;
}

// ---------------------------------------------------------------------------
// Phase 2: one block per output row. Tiny L2-resident reduction + fused MLP.
// ---------------------------------------------------------------------------
__global__ __launch_bounds__(128) void phase2_kernel(
    const float* __restrict__ sq, const float* __restrict__ W1,
    const float* __restrict__ b1, const float* __restrict__ W2,
    const float* __restrict__ b2, float* __restrict__ out)
{
    const int t   = threadIdx.x;
    const int row = blockIdx.x;        // 0..127
    const int b   = row >> 4;
    const int p   = row & 15;

    __shared__ __align__(16) float ri[4 * H_];          // residual input (512)
    __shared__ float massred[NCHUNKS_];
    __shared__ __align__(16) float p1[4][HIDDEN_];      // GEMM1 warp partials
    __shared__ __align__(16) float hd[HIDDEN_];
    __shared__ __align__(16) float p2[8][RDIM_];        // GEMM2 group partials

    // ---------- Stage 1: fold 8 chunk-group partials (L2-resident) ----------
    float s1 = 0.f, s2 = 0.f, mx = neg_inf();
    {
        const float* q = g_part2 + (size_t)row * (3 * NCG_ * H_) + t;
        #pragma unroll
        for (int cg = 0; cg < NCG_; cg++) {
            s1 += q[cg * H_];
            s2 += q[NCG_ * H_ + cg * H_];
            mx = fmaxf(mx, q[2 * NCG_ * H_ + cg * H_]);
        }
        if (t < NCHUNKS_)
            massred[t] = g_massp[(b * NCHUNKS_ + t) * P_ + p];
    }
    __syncthreads();

    // ---------- Stage 2: finalize stats, build residual row ----------
    {
        float sumA = 0.f;
        #pragma unroll
        for (int i = 0; i < NCHUNKS_; i++) sumA += massred[i];   // smem broadcast
        float mass = fmaxf(sumA, EPSV);
        float inv  = 1.f / mass;

        float mu = s1 * inv;
        ri[t]          = sq[(size_t)(b * P_ + p) * H_ + t];
        ri[H_ + t]     = mu;
        ri[2 * H_ + t] = isfinite(mx) ? mx : 0.f;
        ri[3 * H_ + t] = (s2 - 2.f * mu * s1 + mu * mu * sumA) * inv;
    }
    __syncthreads();

    // ---------- GEMM1: 512 x 128, warp-split over K ----------
    {
        const int jq = t & 31;         // output j-quad: j = 4*jq..4*jq+3
        const int kg = t >> 5;         // K group 0..3 (128 k each)
        const float* Wp = W1 + (size_t)(kg * H_) * HIDDEN_ + jq * 4;
        const float* rp = ri + kg * H_;
        float4 accA = make_float4(0.f, 0.f, 0.f, 0.f);
        float4 accB = make_float4(0.f, 0.f, 0.f, 0.f);
        #pragma unroll 8
        for (int k = 0; k < H_; k += 2) {
            float4 w0 = *(const float4*)(Wp + (size_t)k * HIDDEN_);
            float  r0 = rp[k];
            accA.x = fmaf(r0, w0.x, accA.x);
            accA.y = fmaf(r0, w0.y, accA.y);
            accA.z = fmaf(r0, w0.z, accA.z);
            accA.w = fmaf(r0, w0.w, accA.w);
            float4 w1 = *(const float4*)(Wp + (size_t)(k + 1) * HIDDEN_);
            float  r1 = rp[k + 1];
            accB.x = fmaf(r1, w1.x, accB.x);
            accB.y = fmaf(r1, w1.y, accB.y);
            accB.z = fmaf(r1, w1.z, accB.z);
            accB.w = fmaf(r1, w1.w, accB.w);
        }
        float4 acc = make_float4(accA.x + accB.x, accA.y + accB.y,
                                 accA.z + accB.z, accA.w + accB.w);
        *(float4*)&p1[kg][jq * 4] = acc;
    }
    __syncthreads();

    hd[t] = fmaxf(b1[t] + p1[0][t] + p1[1][t] + p1[2][t] + p1[3][t], 0.f);
    __syncthreads();

    // ---------- GEMM2: 128 x 64, 8-way split over K ----------
    {
        const int jq = t & 15;         // j = 4*jq..4*jq+3
        const int kg = t >> 4;         // K group 0..7 (16 k each)
        const float* Wp = W2 + (size_t)(kg * 16) * RDIM_ + jq * 4;
        const float* hp = hd + kg * 16;
        float4 accA = make_float4(0.f, 0.f, 0.f, 0.f);
        float4 accB = make_float4(0.f, 0.f, 0.f, 0.f);
        #pragma unroll
        for (int k = 0; k < 16; k += 2) {
            float4 w0 = *(const float4*)(Wp + (size_t)k * RDIM_);
            float  r0 = hp[k];
            accA.x = fmaf(r0, w0.x, accA.x);
            accA.y = fmaf(r0, w0.y, accA.y);
            accA.z = fmaf(r0, w0.z, accA.z);
            accA.w = fmaf(r0, w0.w, accA.w);
            float4 w1 = *(const float4*)(Wp + (size_t)(k + 1) * RDIM_);
            float  r1 = hp[k + 1];
            accB.x = fmaf(r1, w1.x, accB.x);
            accB.y = fmaf(r1, w1.y, accB.y);
            accB.z = fmaf(r1, w1.z, accB.z);
            accB.w = fmaf(r1, w1.w, accB.w);
        }
        float4 acc = make_float4(accA.x + accB.x, accA.y + accB.y,
                                 accA.z + accB.z, accA.w + accB.w);
        *(float4*)&p2[kg][jq * 4] = acc;
    }
    __syncthreads();

    if (t < RDIM_) {
        float o = b2[t];
        #pragma unroll
        for (int g = 0; g < 8; g++) o += p2[g][t];
        out[(size_t)row * RDIM_ + t] = o;
    }
}

// ---------------------------------------------------------------------------
extern "C" void kernel_launch(void* const* d_in, const int* in_sizes, int n_in,
                              void* d_out, int out_size)
{
    const float* sq = (const float*)d_in[0];
    const float* pf = (const float*)d_in[1];
    const float* am = (const float*)d_in[2];
    const float* W1 = (const float*)d_in[3];
    const float* b1 = (const float*)d_in[4];
    const float* W2 = (const float*)d_in[5];
    const float* b2 = (const float*)d_in[6];
    float* out = (float*)d_out;

    dim3 g1(NCHUNKS_, B_);
    phase1_kernel<<<g1, 128>>>(pf, am);
    reduce_kernel<<<dim3(NCG_, 128), 128>>>();
    phase2_kernel<<<128, 128>>>(sq, W1, b1, W2, b2, out);
}

// round 7
// speedup vs baseline: 1.0559x; 1.0559x over previous
#include <cuda_runtime.h>
#include <math.h>

#define EPSV 1e-6f
#define B_ 8
#define N_ 4096
#define P_ 16
#define H_ 128
#define NC_ 32                 // points per chunk
#define NCHUNKS_ (N_/NC_)      // 128
#define NCG_ 8                 // chunk groups (16 chunks each)
#define HIDDEN_ 128
#define RDIM_ 64
#define PH_ (P_*H_)            // 2048

// scratch
__device__ __align__(16) float g_part[B_ * NCHUNKS_ * 3 * PH_];     // 25.2 MB
__device__ float g_massp[B_ * NCHUNKS_ * P_];
// second-level partials: [row(128)][stat(3)][cg(8)*128 + h]
__device__ __align__(16) float g_part2[128 * 3 * NCG_ * H_];        // 1.5 MB

__device__ __forceinline__ float neg_inf() { return __int_as_float(0xff800000u); }

typedef unsigned long long u64;

__device__ __forceinline__ u64 pk2(float lo, float hi) {
    u64 r; asm("mov.b64 %0, {%1,%2};" : "=l"(r) : "f"(lo), "f"(hi)); return r;
}
__device__ __forceinline__ void upk2(u64 v, float& lo, float& hi) {
    asm("mov.b64 {%0,%1}, %2;" : "=f"(lo), "=f"(hi) : "l"(v));
}
// d = a*b + d  (two independent fp32 FMAs, one FFMA2)
#define FFMA2(d, a, b) asm("fma.rn.f32x2 %0, %1, %2, %0;" : "+l"(d) : "l"(a), "l"(b))
// t = a*b + c
#define FFMA2_3(t, a, b, c) asm("fma.rn.f32x2 %0, %1, %2, %3;" : "=l"(t) : "l"(a), "l"(b), "l"(c))

// ---------------------------------------------------------------------------
// Phase 1: per-(b, n-chunk) weighted sum / sumsq / masked-max partials.
// Packed f32x2 core: p-pair FFMA2 for s1, s2, and the masked-max term.
// ---------------------------------------------------------------------------
__global__ __launch_bounds__(128) void phase1_kernel(
    const float* __restrict__ pf, const float* __restrict__ am)
{
    const int c = blockIdx.x;      // chunk 0..127
    const int b = blockIdx.y;      // batch 0..7
    const int t = threadIdx.x;     // h lane 0..127

    __shared__ __align__(16) float a_sm[NC_][P_];
    __shared__ __align__(16) float q_sm[NC_][P_];   // bias: 0 if active, -inf if not

    // load assign chunk (512 floats = 128 float4) + build bias
    {
        const float4* ap = (const float4*)(am + (size_t)(b * N_ + c * NC_) * P_);
        float4 v = ap[t];
        ((float4*)a_sm)[t] = v;
        float4 qq;
        qq.x = (v.x <= EPSV) ? neg_inf() : 0.f;
        qq.y = (v.y <= EPSV) ? neg_inf() : 0.f;
        qq.z = (v.z <= EPSV) ? neg_inf() : 0.f;
        qq.w = (v.w <= EPSV) ? neg_inf() : 0.f;
        ((float4*)q_sm)[t] = qq;
    }
    __syncthreads();

    u64 s1p[8], s2p[8];
    float mx[16];
    #pragma unroll
    for (int i = 0; i < 8; i++) { s1p[i] = 0ULL; s2p[i] = 0ULL; }
    #pragma unroll
    for (int p = 0; p < P_; p++) mx[p] = neg_inf();

    const float* pfp = pf + (size_t)(b * N_ + c * NC_) * H_ + t;

    #pragma unroll 4
    for (int n = 0; n < NC_; n++) {
        float v  = pfp[n * H_];
        float vv = v * v;
        u64 vp = pk2(v,  v);
        u64 wp = pk2(vv, vv);
        const ulonglong2* ap = (const ulonglong2*)&a_sm[n][0];   // 4 x (2 pairs)
        const ulonglong2* qp = (const ulonglong2*)&q_sm[n][0];
        #pragma unroll
        for (int i = 0; i < 4; i++) {
            ulonglong2 aa = ap[i];
            ulonglong2 qq = qp[i];
            FFMA2(s1p[2 * i],     aa.x, vp);
            FFMA2(s2p[2 * i],     aa.x, wp);
            u64 t0; FFMA2_3(t0, aa.x, vp, qq.x);
            float t0l, t0h; upk2(t0, t0l, t0h);
            mx[4 * i]     = fmaxf(mx[4 * i],     t0l);
            mx[4 * i + 1] = fmaxf(mx[4 * i + 1], t0h);

            FFMA2(s1p[2 * i + 1], aa.y, vp);
            FFMA2(s2p[2 * i + 1], aa.y, wp);
            u64 t1; FFMA2_3(t1, aa.y, vp, qq.y);
            float t1l, t1h; upk2(t1, t1l, t1h);
            mx[4 * i + 2] = fmaxf(mx[4 * i + 2], t1l);
            mx[4 * i + 3] = fmaxf(mx[4 * i + 3], t1h);
        }
    }

    // write partials: layout [b][c][stat][p][h], h contiguous
    float* base = g_part + (size_t)((b * NCHUNKS_ + c) * 3) * PH_ + t;
    #pragma unroll
    for (int i = 0; i < 8; i++) {
        float a0, a1, b0, b1;
        upk2(s1p[i], a0, a1);
        upk2(s2p[i], b0, b1);
        base[0 * PH_ + (2 * i) * H_]     = a0;
        base[0 * PH_ + (2 * i + 1) * H_] = a1;
        base[1 * PH_ + (2 * i) * H_]     = b0;
        base[1 * PH_ + (2 * i + 1) * H_] = b1;
    }
    #pragma unroll
    for (int p = 0; p < P_; p++)
        base[2 * PH_ + p * H_] = mx[p];

    // per-p assign sum for this chunk
    if (t < P_) {
        float s = 0.f;
        #pragma unroll 8
        for (int n = 0; n < NC_; n++) s += a_sm[n][t];
        g_massp[(b * NCHUNKS_ + c) * P_ + t] = s;
    }
}

// ---------------------------------------------------------------------------
// Reduce: fold 128 chunks -> 8 chunk-groups (16 chunks each), high parallelism.
// ---------------------------------------------------------------------------
__global__ __launch_bounds__(128) void reduce_kernel()
{
    const int cg  = blockIdx.x;        // 0..7
    const int row = blockIdx.y;        // 0..127
    const int b   = row >> 4;
    const int p   = row & 15;
    const int t   = threadIdx.x;       // h

    float s1 = 0.f, s2 = 0.f, mx = neg_inf();
    const float* base = g_part
        + (size_t)((b * NCHUNKS_ + cg * 16) * 3) * PH_ + p * H_ + t;
    #pragma unroll
    for (int cc = 0; cc < 16; cc++) {
        const float* bb = base + (size_t)cc * 3 * PH_;
        s1 += bb[0];
        s2 += bb[PH_];
        mx = fmaxf(mx, bb[2 * PH_]);
    }
    float* o = g_part2 + (size_t)row * (3 * NCG_ * H_) + cg * H_ + t;
    o[0]                = s1;
    o[NCG_ * H_]        = s2;
    o[2 * NCG_ * H_]    = mx;
}

// ---------------------------------------------------------------------------
// Phase 2: one block per output row. Tiny L2-resident reduction + fused MLP.
// ---------------------------------------------------------------------------
__global__ __launch_bounds__(128) void phase2_kernel(
    const float* __restrict__ sq, const float* __restrict__ W1,
    const float* __restrict__ b1, const float* __restrict__ W2,
    const float* __restrict__ b2, float* __restrict__ out)
{
    const int t   = threadIdx.x;
    const int row = blockIdx.x;        // 0..127
    const int b   = row >> 4;
    const int p   = row & 15;

    __shared__ __align__(16) float ri[4 * H_];          // residual input (512)
    __shared__ float massred[NCHUNKS_];
    __shared__ __align__(16) float p1[4][HIDDEN_];      // GEMM1 warp partials
    __shared__ __align__(16) float hd[HIDDEN_];
    __shared__ __align__(16) float p2[8][RDIM_];        // GEMM2 group partials

    // ---------- Stage 1: fold 8 chunk-group partials (L2-resident) ----------
    float s1 = 0.f, s2 = 0.f, mx = neg_inf();
    {
        const float* q = g_part2 + (size_t)row * (3 * NCG_ * H_) + t;
        #pragma unroll
        for (int cg = 0; cg < NCG_; cg++) {
            s1 += q[cg * H_];
            s2 += q[NCG_ * H_ + cg * H_];
            mx = fmaxf(mx, q[2 * NCG_ * H_ + cg * H_]);
        }
        massred[t] = g_massp[(b * NCHUNKS_ + t) * P_ + p];
    }
    __syncthreads();

    // ---------- Stage 2: finalize stats, build residual row ----------
    {
        float sumA = 0.f;
        #pragma unroll
        for (int i = 0; i < NCHUNKS_; i++) sumA += massred[i];   // smem broadcast
        float mass = fmaxf(sumA, EPSV);
        float inv  = 1.f / mass;

        float mu = s1 * inv;
        ri[t]          = sq[(size_t)(b * P_ + p) * H_ + t];
        ri[H_ + t]     = mu;
        ri[2 * H_ + t] = isfinite(mx) ? mx : 0.f;
        ri[3 * H_ + t] = (s2 - 2.f * mu * s1 + mu * mu * sumA) * inv;
    }
    __syncthreads();

    // ---------- GEMM1: 512 x 128, warp-split over K ----------
    {
        const int jq = t & 31;         // output j-quad: j = 4*jq..4*jq+3
        const int kg = t >> 5;         // K group 0..3 (128 k each)
        const float* Wp = W1 + (size_t)(kg * H_) * HIDDEN_ + jq * 4;
        const float* rp = ri + kg * H_;
        float4 accA = make_float4(0.f, 0.f, 0.f, 0.f);
        float4 accB = make_float4(0.f, 0.f, 0.f, 0.f);
        #pragma unroll 8
        for (int k = 0; k < H_; k += 2) {
            float4 w0 = *(const float4*)(Wp + (size_t)k * HIDDEN_);
            float  r0 = rp[k];
            accA.x = fmaf(r0, w0.x, accA.x);
            accA.y = fmaf(r0, w0.y, accA.y);
            accA.z = fmaf(r0, w0.z, accA.z);
            accA.w = fmaf(r0, w0.w, accA.w);
            float4 w1 = *(const float4*)(Wp + (size_t)(k + 1) * HIDDEN_);
            float  r1 = rp[k + 1];
            accB.x = fmaf(r1, w1.x, accB.x);
            accB.y = fmaf(r1, w1.y, accB.y);
            accB.z = fmaf(r1, w1.z, accB.z);
            accB.w = fmaf(r1, w1.w, accB.w);
        }
        float4 acc = make_float4(accA.x + accB.x, accA.y + accB.y,
                                 accA.z + accB.z, accA.w + accB.w);
        *(float4*)&p1[kg][jq * 4] = acc;
    }
    __syncthreads();

    hd[t] = fmaxf(b1[t] + p1[0][t] + p1[1][t] + p1[2][t] + p1[3][t], 0.f);
    __syncthreads();

    // ---------- GEMM2: 128 x 64, 8-way split over K ----------
    {
        const int jq = t & 15;         // j = 4*jq..4*jq+3
        const int kg = t >> 4;         // K group 0..7 (16 k each)
        const float* Wp = W2 + (size_t)(kg * 16) * RDIM_ + jq * 4;
        const float* hp = hd + kg * 16;
        float4 accA = make_float4(0.f, 0.f, 0.f, 0.f);
        float4 accB = make_float4(0.f, 0.f, 0.f, 0.f);
        #pragma unroll
        for (int k = 0; k < 16; k += 2) {
            float4 w0 = *(const float4*)(Wp + (size_t)k * RDIM_);
            float  r0 = hp[k];
            accA.x = fmaf(r0, w0.x, accA.x);
            accA.y = fmaf(r0, w0.y, accA.y);
            accA.z = fmaf(r0, w0.z, accA.z);
            accA.w = fmaf(r0, w0.w, accA.w);
            float4 w1 = *(const float4*)(Wp + (size_t)(k + 1) * RDIM_);
            float  r1 = hp[k + 1];
            accB.x = fmaf(r1, w1.x, accB.x);
            accB.y = fmaf(r1, w1.y, accB.y);
            accB.z = fmaf(r1, w1.z, accB.z);
            accB.w = fmaf(r1, w1.w, accB.w);
        }
        float4 acc = make_float4(accA.x + accB.x, accA.y + accB.y,
                                 accA.z + accB.z, accA.w + accB.w);
        *(float4*)&p2[kg][jq * 4] = acc;
    }
    __syncthreads();

    if (t < RDIM_) {
        float o = b2[t];
        #pragma unroll
        for (int g = 0; g < 8; g++) o += p2[g][t];
        out[(size_t)row * RDIM_ + t] = o;
    }
}

// ---------------------------------------------------------------------------
extern "C" void kernel_launch(void* const* d_in, const int* in_sizes, int n_in,
                              void* d_out, int out_size)
{
    const float* sq = (const float*)d_in[0];
    const float* pf = (const float*)d_in[1];
    const float* am = (const float*)d_in[2];
    const float* W1 = (const float*)d_in[3];
    const float* b1 = (const float*)d_in[4];
    const float* W2 = (const float*)d_in[5];
    const float* b2 = (const float*)d_in[6];
    float* out = (float*)d_out;

    dim3 g1(NCHUNKS_, B_);
    phase1_kernel<<<g1, 128>>>(pf, am);
    reduce_kernel<<<dim3(NCG_, 128), 128>>>();
    phase2_kernel<<<128, 128>>>(sq, W1, b1, W2, b2, out);
}